// round 4
// baseline (speedup 1.0000x reference)
#include <cuda_runtime.h>

#define B_ 64
#define T_ 1024
#define C_ 2
#define N_ 128
#define RPAD 36   // 32 rows + 4 pad floats per quarter -> conflict-free quarters

// ---- packed f32x2 helpers (Blackwell sm_100+) ----
__device__ __forceinline__ unsigned long long pk2(float lo, float hi) {
    unsigned long long r;
    asm("mov.b64 %0, {%1, %2};" : "=l"(r) : "f"(lo), "f"(hi));
    return r;
}
__device__ __forceinline__ void upk2(unsigned long long v, float& lo, float& hi) {
    asm("mov.b64 {%0, %1}, %2;" : "=f"(lo), "=f"(hi) : "l"(v));
}
__device__ __forceinline__ void fma2(unsigned long long& acc, unsigned long long a,
                                     unsigned long long b) {
    asm("fma.rn.f32x2 %0, %1, %2, %0;" : "+l"(acc) : "l"(a), "l"(b));
}
__device__ __forceinline__ unsigned long long add2(unsigned long long a,
                                                   unsigned long long b) {
    unsigned long long r;
    asm("add.rn.f32x2 %0, %1, %2;" : "=l"(r) : "l"(a), "l"(b));
    return r;
}

// Quarter-dot: sum over 32 rows held in rq[0..31] (16B-aligned SMEM),
// e2[m] packs this thread's E rows (2m, 2m+1) for its column.
__device__ __forceinline__ float dot32(const float* rq,
                                       const unsigned long long* e2) {
    unsigned long long a0 = 0ull, a1 = 0ull;
    const ulonglong2* pv = reinterpret_cast<const ulonglong2*>(rq);
#pragma unroll
    for (int k = 0; k < 8; ++k) {        // 8 * 4 floats = 32 rows
        ulonglong2 v = pv[k];
        fma2(a0, e2[2 * k],     v.x);
        fma2(a1, e2[2 * k + 1], v.y);
    }
    a0 = add2(a0, a1);
    float lo, hi;
    upk2(a0, lo, hi);
    return lo + hi;
}

__global__ void __launch_bounds__(512, 1)
crf_fwd_kernel(const float* __restrict__ emissions,   // [B,T,C,N]
               const int*   __restrict__ lengths,     // [B]
               const float* __restrict__ trans,       // [1,C,N,N]
               const float* __restrict__ start_t,     // [1,C,N]
               const float* __restrict__ end_t,       // [1,C,N]
               float*       __restrict__ out)         // [B,C]
{
    const int tid  = threadIdx.x;
    const int q    = tid & 3;           // row-quarter this thread sums
    const int j    = tid >> 2;          // tag column this thread owns
    const int lane = tid & 31;
    const int wrp  = tid >> 5;
    const int bc   = blockIdx.x;        // chain id
    const int b    = bc >> 1;
    const int c    = bc & 1;
    const int len  = lengths[b];        // in [T/2, T]

    __shared__ __align__(16) float r_sh[2][4][RPAD];  // [buf][quarter][row]
    __shared__ __align__(16) float red_sh[16];

    // ---- E packed: e2[m] = (exp(trans[c, q*32+2m, j]), exp(trans[c, q*32+2m+1, j])) ----
    unsigned long long e2[16];
    {
        const float* tb = trans + (size_t)c * N_ * N_ + (size_t)(q * 32) * N_ + j;
#pragma unroll
        for (int m = 0; m < 16; ++m) {
            float lo = __expf(tb[(size_t)(2 * m) * N_]);
            float hi = __expf(tb[(size_t)(2 * m + 1) * N_]);
            e2[m] = pk2(lo, hi);
        }
    }

    const float* ebase = emissions + ((size_t)b * T_ * C_ + c) * N_ + j;
    const int estride = C_ * N_;

    // ---- init: r_0 = exp(start + emit_0) into buffer 0 (padded layout) ----
    if (q == 0)
        r_sh[0][j >> 5][j & 31] = __expf(start_t[c * N_ + j] + ebase[0]);
    float logK = 0.f;
    __syncthreads();

    // ---- emission prefetch ring (pre-exponentiated), slot (t & 3) ----
    float ering[4];
    ering[1] = __expf(__ldg(ebase + (size_t)1 * estride));
    ering[2] = __expf(__ldg(ebase + (size_t)2 * estride));
    ering[3] = __expf(__ldg(ebase + (size_t)3 * estride));
    ering[0] = __expf(__ldg(ebase + (size_t)4 * estride));

    // ---- main scan: steps t = 1 .. len-1, early exit (len uniform per CTA) ----
    int t = 1;
#pragma unroll 1
    for (; t + 3 < len; t += 4) {       // t stays ≡ 1 (mod 4)
#pragma unroll
        for (int u = 0; u < 4; ++u) {
            const int cur  = (1 + u) & 1;   // compile-time buffer parity
            const int prv  = cur ^ 1;
            const int slot = (1 + u) & 3;
            const int tq   = t + u;

            // uniform normalizer from previous step (broadcast LDS)
            float cn  = r_sh[prv][0][0];
            float inv = __fdividef(1.0f, cn);
            logK += __logf(cn);             // off critical path

            // emission: consume + refill 4 ahead (pre-exp'd, clamped)
            float em = ering[slot];
            int tt = tq + 4; tt = (tt > T_ - 1) ? (T_ - 1) : tt;
            ering[slot] = __expf(__ldg(ebase + (size_t)tt * estride));

            // quarter-dot + in-warp combine (lanes 4j..4j+3 hold the 4 partials)
            float S = dot32(r_sh[prv][q], e2);
            S += __shfl_xor_sync(0xffffffffu, S, 1);
            S += __shfl_xor_sync(0xffffffffu, S, 2);

            if (q == 0)
                r_sh[cur][j >> 5][j & 31] = S * em * inv;
            __syncthreads();
        }
    }
    // tail (≤ 3 steps), runtime parity
#pragma unroll 1
    for (; t < len; ++t) {
        const int cur = t & 1;
        const int prv = cur ^ 1;
        float cn  = r_sh[prv][0][0];
        float inv = __fdividef(1.0f, cn);
        logK += __logf(cn);
        float em = ering[t & 3];
        float S = dot32(r_sh[prv][q], e2);
        S += __shfl_xor_sync(0xffffffffu, S, 1);
        S += __shfl_xor_sync(0xffffffffu, S, 2);
        if (q == 0)
            r_sh[cur][j >> 5][j & 31] = S * em * inv;
        __syncthreads();
    }

    // ---- finalize: logZ = logK + log( sum_j r_j * exp(end_j) ) ----
    const int fb = (len - 1) & 1;
    float v = 0.f;
    if (q == 0)
        v = r_sh[fb][j >> 5][j & 31] * __expf(end_t[c * N_ + j]);
#pragma unroll
    for (int o = 16; o > 0; o >>= 1)
        v += __shfl_xor_sync(0xffffffffu, v, o);
    if (lane == 0) red_sh[wrp] = v;
    __syncthreads();
    if (tid == 0) {
        float Sf = 0.f;
#pragma unroll
        for (int w = 0; w < 16; ++w) Sf += red_sh[w];
        out[bc] = logK + logf(Sf);
    }
}

extern "C" void kernel_launch(void* const* d_in, const int* in_sizes, int n_in,
                              void* d_out, int out_size) {
    // Identify inputs by element count (robust to metadata ordering).
    const float* emissions = nullptr;
    const int*   lengths   = nullptr;
    const float* trans     = nullptr;
    const float* start_t   = nullptr;
    const float* end_t     = nullptr;

    for (int i = 0; i < n_in; ++i) {
        int sz = in_sizes[i];
        if (sz == B_ * T_ * C_ * N_)      emissions = (const float*)d_in[i];
        else if (sz == B_)                lengths   = (const int*)d_in[i];
        else if (sz == C_ * N_ * N_)      trans     = (const float*)d_in[i];
    }
    if (n_in > 3 && in_sizes[3] == C_ * N_) start_t = (const float*)d_in[3];
    for (int i = 0; i < n_in; ++i) {
        if (in_sizes[i] == C_ * N_ && (const float*)d_in[i] != start_t)
            end_t = (const float*)d_in[i];
    }
    if (!start_t) {
        for (int i = 0; i < n_in; ++i)
            if (in_sizes[i] == C_ * N_) { start_t = (const float*)d_in[i]; break; }
        for (int i = 0; i < n_in; ++i)
            if (in_sizes[i] == C_ * N_ && (const float*)d_in[i] != start_t)
                end_t = (const float*)d_in[i];
    }

    float* out = (float*)d_out;
    crf_fwd_kernel<<<B_ * C_, 512>>>(emissions, lengths, trans, start_t, end_t, out);
}

// round 5
// speedup vs baseline: 1.8390x; 1.8390x over previous
#include <cuda_runtime.h>

#define B_ 64
#define T_ 1024
#define C_ 2
#define N_ 128

// ---- packed f32x2 helpers (Blackwell sm_100+) ----
__device__ __forceinline__ unsigned long long pk2(float lo, float hi) {
    unsigned long long r;
    asm("mov.b64 %0, {%1, %2};" : "=l"(r) : "f"(lo), "f"(hi));
    return r;
}
__device__ __forceinline__ void upk2(unsigned long long v, float& lo, float& hi) {
    asm("mov.b64 {%0, %1}, %2;" : "=f"(lo), "=f"(hi) : "l"(v));
}
__device__ __forceinline__ void fma2(unsigned long long& acc, unsigned long long a,
                                     unsigned long long b) {
    asm("fma.rn.f32x2 %0, %1, %2, %0;" : "+l"(acc) : "l"(a), "l"(b));
}
__device__ __forceinline__ unsigned long long add2(unsigned long long a,
                                                   unsigned long long b) {
    unsigned long long r;
    asm("add.rn.f32x2 %0, %1, %2;" : "=l"(r) : "l"(a), "l"(b));
    return r;
}

// Packed dot over ALL 128 rows: S_j = sum_i r_i * E_ij.
__device__ __forceinline__ float dot128(const float* rbuf,
                                        const unsigned long long* e2) {
    unsigned long long a0 = 0ull, a1 = 0ull, a2 = 0ull, a3 = 0ull;
    const ulonglong2* pv = reinterpret_cast<const ulonglong2*>(rbuf);
#pragma unroll
    for (int k = 0; k < 32; ++k) {       // 32 * 4 floats = 128 rows
        ulonglong2 v = pv[k];
        if ((k & 1) == 0) { fma2(a0, e2[2 * k], v.x); fma2(a1, e2[2 * k + 1], v.y); }
        else              { fma2(a2, e2[2 * k], v.x); fma2(a3, e2[2 * k + 1], v.y); }
    }
    a0 = add2(a0, a1);
    a2 = add2(a2, a3);
    a0 = add2(a0, a2);
    float lo, hi;
    upk2(a0, lo, hi);
    return lo + hi;
}

__global__ void __launch_bounds__(128, 1)
crf_fwd_kernel(const float* __restrict__ emissions,   // [B,T,C,N]
               const int*   __restrict__ lengths,     // [B]
               const float* __restrict__ trans,       // [1,C,N,N]
               const float* __restrict__ start_t,     // [1,C,N]
               const float* __restrict__ end_t,       // [1,C,N]
               float*       __restrict__ out)         // [B,C]
{
    const int j   = threadIdx.x;        // tag column this thread owns
    const int bc  = blockIdx.x;         // chain id
    const int b   = bc >> 1;
    const int c   = bc & 1;
    const int wid = j >> 5;
    const int len = lengths[b];         // in [T/2, T]

    __shared__ __align__(16) float r_sh[2][N_];
    __shared__ __align__(16) float red_sh[4];

    // ---- E packed: e2[m] = (exp(trans[c,2m,j]), exp(trans[c,2m+1,j])) ----
    unsigned long long e2[64];
    {
        const float* tb = trans + (size_t)c * N_ * N_ + j;
#pragma unroll
        for (int m = 0; m < 64; ++m) {
            float lo = __expf(tb[(size_t)(2 * m) * N_]);
            float hi = __expf(tb[(size_t)(2 * m + 1) * N_]);
            e2[m] = pk2(lo, hi);
        }
    }

    const float* ebase = emissions + ((size_t)b * T_ * C_ + c) * N_ + j;
    const int estride = C_ * N_;

    // ---- init: r_0 = exp(start + emit_0), unnormalized ----
    r_sh[0][j] = __expf(start_t[c * N_ + j] + ebase[0]);
    float logK = 0.f;
    __syncthreads();

    // ---- RAW emission prefetch ring, depth 8: slot (t & 7) holds raw emit_t.
    //      __expf is applied only at consumption (8 steps after the load),
    //      so the LDG scoreboard never stalls the critical path. ----
    float ering[8];
#pragma unroll
    for (int d = 1; d <= 8; ++d) {
        int tt = d; tt = (tt > T_ - 1) ? (T_ - 1) : tt;
        ering[d & 7] = __ldg(ebase + (size_t)tt * estride);
    }

    // ---- main scan: steps t = 1 .. len-1, early exit (len uniform per CTA) ----
    int t = 1;
#pragma unroll 1
    for (; t + 7 < len; t += 8) {       // t stays ≡ 1 (mod 8)
#pragma unroll
        for (int u = 0; u < 8; ++u) {
            const int cur  = (1 + u) & 1;   // compile-time buffer parity
            const int prv  = cur ^ 1;
            const int slot = (1 + u) & 7;   // compile-time ring slot
            const int tq   = t + u;

            // uniform normalizer from previous step (broadcast LDS)
            float cn  = r_sh[prv][0];
            float inv = __fdividef(1.0f, cn);
            logK += __logf(cn);             // off critical path (accumulator only)

            // emission: exp of an 8-step-old raw value; refill 8 ahead (raw)
            float em = __expf(ering[slot]);
            int tt = tq + 8; tt = (tt > T_ - 1) ? (T_ - 1) : tt;
            ering[slot] = __ldg(ebase + (size_t)tt * estride);

            float S = dot128(r_sh[prv], e2);
            r_sh[cur][j] = S * em * inv;
            __syncthreads();
        }
    }
    // tail (≤ 7 steps), runtime parity
#pragma unroll 1
    for (; t < len; ++t) {
        const int cur = t & 1;
        const int prv = cur ^ 1;
        float cn  = r_sh[prv][0];
        float inv = __fdividef(1.0f, cn);
        logK += __logf(cn);
        float em = __expf(ering[t & 7]);
        int tt = t + 8; tt = (tt > T_ - 1) ? (T_ - 1) : tt;
        ering[t & 7] = __ldg(ebase + (size_t)tt * estride);
        float S = dot128(r_sh[prv], e2);
        r_sh[cur][j] = S * em * inv;
        __syncthreads();
    }

    // ---- finalize: logZ = logK + log( sum_j r_j * exp(end_j) ) ----
    float v = r_sh[(len - 1) & 1][j] * __expf(end_t[c * N_ + j]);
    float s = v;
#pragma unroll
    for (int o = 16; o > 0; o >>= 1)
        s += __shfl_xor_sync(0xffffffffu, s, o);
    if ((j & 31) == 0) red_sh[wid] = s;
    __syncthreads();
    if (j == 0) {
        float Sf = (red_sh[0] + red_sh[1]) + (red_sh[2] + red_sh[3]);
        out[bc] = logK + logf(Sf);
    }
}

extern "C" void kernel_launch(void* const* d_in, const int* in_sizes, int n_in,
                              void* d_out, int out_size) {
    // Identify inputs by element count (robust to metadata ordering).
    const float* emissions = nullptr;
    const int*   lengths   = nullptr;
    const float* trans     = nullptr;
    const float* start_t   = nullptr;
    const float* end_t     = nullptr;

    for (int i = 0; i < n_in; ++i) {
        int sz = in_sizes[i];
        if (sz == B_ * T_ * C_ * N_)      emissions = (const float*)d_in[i];
        else if (sz == B_)                lengths   = (const int*)d_in[i];
        else if (sz == C_ * N_ * N_)      trans     = (const float*)d_in[i];
    }
    if (n_in > 3 && in_sizes[3] == C_ * N_) start_t = (const float*)d_in[3];
    for (int i = 0; i < n_in; ++i) {
        if (in_sizes[i] == C_ * N_ && (const float*)d_in[i] != start_t)
            end_t = (const float*)d_in[i];
    }
    if (!start_t) {
        for (int i = 0; i < n_in; ++i)
            if (in_sizes[i] == C_ * N_) { start_t = (const float*)d_in[i]; break; }
        for (int i = 0; i < n_in; ++i)
            if (in_sizes[i] == C_ * N_ && (const float*)d_in[i] != start_t)
                end_t = (const float*)d_in[i];
    }

    float* out = (float*)d_out;
    crf_fwd_kernel<<<B_ * C_, N_>>>(emissions, lengths, trans, start_t, end_t, out);
}